// round 14
// baseline (speedup 1.0000x reference)
#include <cuda_runtime.h>
#include <cuda_bf16.h>
#include <cmath>

#define BATCH 32
#define NPTS  1024
#define FDIM  7
#define HID   256
#define MLP_H 64
#define OUTD  8

// ---------------- scratch (device globals) ----------------
__device__ unsigned g_adjw[BATCH*32*NPTS];        // adjacency bitmask, 4 MB
__device__ float    g_maxpart[BATCH*8];
__device__ float    g_mlpPart[BATCH*7*MLP_H];
__device__ float    g_upart[BATCH*8*HID];
__device__ float    g_E[OUTD*HID];                // folded GCN head: Wp_gcn@Wfc@W2
__device__ float    g_c0[OUTD];                   // folded GCN bias contribution

// ---------------- kAdj: adjacency only — upper-tri tiles, sign-bit build, transpose mirror ----------------
// grid (8, BATCH) x 512thr; 2 blocks/SM resident -> 8 warps/SMSP
__global__ void __launch_bounds__(512, 2)
kAdj(const float* __restrict__ x, float C) {
    const int tid = threadIdx.x;
    const int lane = tid & 31, w = tid >> 5;      // 16 warps
    const int b = blockIdx.y, sl = blockIdx.x;    // slice 0..7
    __shared__ float4 S4[NPTS];                   // 16KB
    __shared__ float wred[16];

    for (int i = tid; i < NPTS; i += 512) {
        const float* xp = x + (size_t)(b*NPTS + i)*FDIM;
        const float p0 = xp[1], p1 = xp[2];
        const float n = fmaf(p0, p0, p1*p1);
        S4[i] = make_float4(p0, p1, n, C - n);
    }
    __syncthreads();

    const int ww = sl*16 + w;                     // warp id within batch, 0..127
    int L = (ww*528) >> 7;
    const int Lend = ((ww + 1)*528) >> 7;         // ~4.1 tiles per warp

    // decode L -> (jb, kb), kb >= jb
    int jb = 0, rem = L;
    while (rem >= 32 - jb) { rem -= 32 - jb; jb++; }
    int kb = jb + rem;

    unsigned* __restrict__ aw = &g_adjw[(size_t)b*32*NPTS];
    float mx0 = -1e30f, mx1 = -1e30f;             // track max(d2 - C)

    for (; L < Lend; L++) {
        const float4 pk = S4[kb*32 + lane];
        const float a0 = -2.0f*pk.x, a1 = -2.0f*pk.y, nk = pk.z;
        const float4* Pj = &S4[jb*32];

        unsigned w0 = 0, w1 = 0;
        #pragma unroll
        for (int t = 0; t < 32; t++) {
            const float4 pj = Pj[t];                      // broadcast LDS.128
            float u = fmaf(a0, pj.x, nk);
            u = fmaf(a1, pj.y, u);                        // u = nk - 2 pj.pk
            const float dlt = u - pj.w;                   // = d2 - C; sign <=> d2 < C
            const unsigned bit = (__float_as_uint(dlt) >> (31 - t)) & (1u << t);
            if (t & 1) { w1 |= bit; mx1 = fmaxf(mx1, dlt); }
            else       { w0 |= bit; mx0 = fmaxf(mx0, dlt); }
        }
        const unsigned word = w0 | w1;
        aw[(jb << 10) + kb*32 + lane] = word;             // row kb*32+lane, colblock jb

        if (jb != kb) {
            // warp 32x32 bit-matrix transpose (mirror tile)
            unsigned xw = word;
            #pragma unroll
            for (int i2 = 4; i2 >= 0; i2--) {
                const int s = 1 << i2;
                const unsigned msk = (i2 == 4) ? 0x0000FFFFu :
                                     (i2 == 3) ? 0x00FF00FFu :
                                     (i2 == 2) ? 0x0F0F0F0Fu :
                                     (i2 == 1) ? 0x33333333u : 0x55555555u;
                const unsigned y = __shfl_xor_sync(0xffffffffu, xw, s);
                xw = (lane & s) ? ((xw & ~msk) | ((y >> s) & msk))
                                : ((xw & msk) | ((y & msk) << s));
            }
            aw[(kb << 10) + jb*32 + lane] = xw;           // row jb*32+lane, colblock kb
        }
        if (++kb == 32) { jb++; kb = jb; }
    }

    float dmax = fmaxf(mx0, mx1);
    #pragma unroll
    for (int s = 16; s > 0; s >>= 1)
        dmax = fmaxf(dmax, __shfl_xor_sync(0xffffffffu, dmax, s));
    if (lane == 0) wred[w] = dmax;
    __syncthreads();
    if (tid == 0) {
        float mx = wred[0];
        #pragma unroll
        for (int i = 1; i < 16; i++) mx = fmaxf(mx, wred[i]);
        g_maxpart[b*8 + sl] = C + mx;                     // back to max(d2)
    }
}

// ---------------- kMlp1: MLP layer-1 partials ----------------
__global__ void __launch_bounds__(512)
kMlp1(const float* __restrict__ x, const float* __restrict__ Wm0) {
    const int tid = threadIdx.x;
    const int lane = tid & 31, w = tid >> 5;
    const int sl = blockIdx.x, b0 = blockIdx.y*4;
    __shared__ float4 sx[4][256];                 // 16KB

    for (int q = tid; q < 1024; q += 512) {
        const int bb = q >> 8, e = q & 255;
        sx[bb][e] = ((const float4*)(x + (size_t)(b0 + bb)*(NPTS*FDIM) + sl*1024))[e];
    }
    __syncthreads();

    const int h0 = w*4;
    float acc[4][4];
    #pragma unroll
    for (int r = 0; r < 4; r++)
        #pragma unroll
        for (int bb = 0; bb < 4; bb++) acc[r][bb] = 0.f;

    #pragma unroll
    for (int it = 0; it < 8; it++) {
        const int e = it*32 + lane;
        const float4 x0 = sx[0][e], x1 = sx[1][e], x2 = sx[2][e], x3 = sx[3][e];
        #pragma unroll
        for (int r = 0; r < 4; r++) {
            const float4 wv = ((const float4*)(Wm0 + (size_t)(h0 + r)*(NPTS*FDIM) + sl*1024))[e];
            acc[r][0] = fmaf(wv.x, x0.x, acc[r][0]); acc[r][0] = fmaf(wv.y, x0.y, acc[r][0]);
            acc[r][0] = fmaf(wv.z, x0.z, acc[r][0]); acc[r][0] = fmaf(wv.w, x0.w, acc[r][0]);
            acc[r][1] = fmaf(wv.x, x1.x, acc[r][1]); acc[r][1] = fmaf(wv.y, x1.y, acc[r][1]);
            acc[r][1] = fmaf(wv.z, x1.z, acc[r][1]); acc[r][1] = fmaf(wv.w, x1.w, acc[r][1]);
            acc[r][2] = fmaf(wv.x, x2.x, acc[r][2]); acc[r][2] = fmaf(wv.y, x2.y, acc[r][2]);
            acc[r][2] = fmaf(wv.z, x2.z, acc[r][2]); acc[r][2] = fmaf(wv.w, x2.w, acc[r][2]);
            acc[r][3] = fmaf(wv.x, x3.x, acc[r][3]); acc[r][3] = fmaf(wv.y, x3.y, acc[r][3]);
            acc[r][3] = fmaf(wv.z, x3.z, acc[r][3]); acc[r][3] = fmaf(wv.w, x3.w, acc[r][3]);
        }
    }
    #pragma unroll
    for (int r = 0; r < 4; r++)
        #pragma unroll
        for (int bb = 0; bb < 4; bb++) {
            float v = acc[r][bb];
            #pragma unroll
            for (int s = 16; s > 0; s >>= 1) v += __shfl_xor_sync(0xffffffffu, v, s);
            if (lane == 0) g_mlpPart[((b0 + bb)*7 + sl)*MLP_H + h0 + r] = v;
        }
}

// ---------------- kFold: GCN-head fold E[o,:] = (Wp_gcn[o,:]@Wfc)@W2 ----------------
__global__ void __launch_bounds__(512)
kFold(const float* __restrict__ Wfc, const float* __restrict__ W2,
      const float* __restrict__ b2, const float* __restrict__ bfc,
      const float* __restrict__ Wp) {
    const int tid = threadIdx.x;
    const int lane = tid & 31, w = tid >> 5;
    const int o = blockIdx.x;
    __shared__ float sA[HID];
    __shared__ float wred[16];

    const float* wp = Wp + (size_t)o*(MLP_H + HID + OUTD) + MLP_H;   // Wp_gcn row o

    if (tid < HID) {
        float a = 0.f;
        #pragma unroll 8
        for (int k = 0; k < HID; k++)
            a = fmaf(wp[k], Wfc[(size_t)k*HID + tid], a);
        sA[tid] = a;
    }
    __syncthreads();

    float v = (tid < HID) ? fmaf(sA[tid], b2[tid], wp[tid]*bfc[tid]) : 0.f;
    #pragma unroll
    for (int s = 16; s > 0; s >>= 1) v += __shfl_xor_sync(0xffffffffu, v, s);
    if (lane == 0) wred[w] = v;
    __syncthreads();
    if (tid == 0) {
        float c = 0.f;
        #pragma unroll
        for (int i = 0; i < 8; i++) c += wred[i];
        g_c0[o] = c;
    }

    if (tid < HID) {
        float e = 0.f;
        #pragma unroll 8
        for (int k = 0; k < HID; k++)
            e = fmaf(sA[k], W2[(size_t)k*HID + tid], e);
        g_E[o*HID + tid] = e;
    }
}

// ---------------- K2a: degrees + gather (2 thr/row) + u-partials ----------------
__global__ void __launch_bounds__(512)
k2a(const float* __restrict__ x,
    const float* __restrict__ W1, const float* __restrict__ b1) {
    const int q = blockIdx.x, b = blockIdx.y;     // quarter q of batch b
    const int t = threadIdx.x;

    __shared__ float sp0[NPTS], sp1[NPTS], sdv[NPTS];
    __shared__ float4 P4[256];                    // (pp0, pp1, cc, 0) for own rows
    __shared__ float g0[256], g1[256], g2[256];   // half-1 gather partials

    for (int i = t; i < NPTS; i += 512) {
        const float* xp = x + (size_t)(b*NPTS + i)*FDIM;
        sp0[i] = xp[1];
        sp1[i] = xp[2];
    }
    for (int r = t; r < NPTS; r += 512) {
        int cnt = 0;
        #pragma unroll
        for (int cb = 0; cb < 32; cb++)
            cnt += __popc(g_adjw[((size_t)b*32 + cb)*NPTS + r]);
        sdv[r] = 1.0f / sqrtf((float)cnt);
    }
    __syncthreads();

    const int rloc = t & 255;
    const int rr   = q*256 + rloc;
    const int half = t >> 8;
    float s0 = 0.f, s1 = 0.f, ss = 0.f;
    for (int cb = half*16; cb < half*16 + 16; cb++) {
        unsigned m = g_adjw[((size_t)b*32 + cb)*NPTS + rr];
        const int base = cb*32;
        while (m) {
            const int i = __ffs(m) - 1;
            m &= m - 1;
            const int k = base + i;
            const float d = sdv[k];
            s0 = fmaf(d, sp0[k], s0);
            s1 = fmaf(d, sp1[k], s1);
            ss += d;
        }
    }
    if (half == 1) { g0[rloc] = s0; g1[rloc] = s1; g2[rloc] = ss; }
    __syncthreads();
    if (half == 0) {
        const float dj = sdv[rr];
        P4[rloc] = make_float4(dj*(s0 + g0[rloc]), dj*(s1 + g1[rloc]),
                               dj*(ss + g2[rloc]), 0.f);
    }
    __syncthreads();

    {
        const int d = t & 255;
        const float w0 = W1[2*d], w1 = W1[2*d + 1], bd = b1[d];
        const int pb = half*128;
        float a0 = 0.f, a1 = 0.f;
        #pragma unroll 4
        for (int i = 0; i < 64; i++) {
            const float4 v0 = P4[pb + i];
            const float4 v1 = P4[pb + 64 + i];
            float t0 = fmaf(w1, v0.y, fmaf(w0, v0.x, bd)); t0 = fmaxf(t0, 0.f);
            float t1 = fmaf(w1, v1.y, fmaf(w0, v1.x, bd)); t1 = fmaxf(t1, 0.f);
            a0 = fmaf(v0.z, t0, a0);
            a1 = fmaf(v1.z, t1, a1);
        }
        g_upart[((size_t)b*8 + q*2 + half)*HID + d] = a0 + a1;
    }
}

// ---------------- K2b: speed, m, glo, mlp finish, folded-head output ----------------
__global__ void __launch_bounds__(1024)
k2b(const float* __restrict__ x,
    const float* __restrict__ Wg, const float* __restrict__ bgv,
    const float* __restrict__ Wm1, const float* __restrict__ bm1,
    const float* __restrict__ bm0,
    const float* __restrict__ Wp, const float* __restrict__ bp,
    float* __restrict__ out) {
    const int b = blockIdx.x;
    const int t = threadIdx.x;
    const int lane = t & 31, wid = t >> 5;

    __shared__ float red[32];
    __shared__ float sm[HID];
    __shared__ float m0[MLP_H], m1[MLP_H], glo8[OUTD];
    __shared__ float sgl[2];

    {
        const float* xp = x + (size_t)(b*NPTS + t)*FDIM;
        const float x3 = xp[3], x4 = xp[4];
        float sp = sqrtf(fmaf(x3, x3, x4*x4));
        #pragma unroll
        for (int s = 16; s > 0; s >>= 1) sp += __shfl_xor_sync(0xffffffffu, sp, s);
        if (lane == 0) red[wid] = sp;
    }
    if (t < HID) {
        float u = 0.f;
        #pragma unroll
        for (int c = 0; c < 8; c++) u += g_upart[((size_t)b*8 + c)*HID + t];
        sm[t] = u * (1.0f/1024.0f);
    } else if (t >= 512 && t < 512 + MLP_H) {
        const int h = t - 512;
        float a = bm0[h];
        #pragma unroll
        for (int s = 0; s < 7; s++) a += g_mlpPart[(b*7 + s)*MLP_H + h];
        m0[h] = fmaxf(a, 0.f);
    }
    __syncthreads();

    if (wid == 0) {
        float v = red[lane];
        #pragma unroll
        for (int s = 16; s > 0; s >>= 1) v += __shfl_xor_sync(0xffffffffu, v, s);
        if (lane == 0) {
            float mx = g_maxpart[b*8];
            #pragma unroll
            for (int i = 1; i < 8; i++) mx = fmaxf(mx, g_maxpart[b*8 + i]);
            sgl[0] = v * (1.0f/1024.0f);
            sgl[1] = 1.0f / sqrtf(mx);
        }
    }
    __syncthreads();

    if (t >= 768 && t < 768 + OUTD) {
        const int o = t - 768;
        const float ge = fmaf(Wg[2*o], sgl[0], fmaf(Wg[2*o + 1], sgl[1], bgv[o]));
        glo8[o] = fmaxf(ge, 0.f);
    }
    if (t < 256) {
        const int od = t >> 2, qq = t & 3;
        const float4* wr4 = (const float4*)(Wm1 + (size_t)od*MLP_H + qq*16);
        const float4* mm4 = (const float4*)(m0 + qq*16);
        float p = 0.f;
        #pragma unroll
        for (int e = 0; e < 4; e++) {
            const float4 wv = wr4[e], mv = mm4[e];
            p = fmaf(wv.x, mv.x, p); p = fmaf(wv.y, mv.y, p);
            p = fmaf(wv.z, mv.z, p); p = fmaf(wv.w, mv.w, p);
        }
        p += __shfl_xor_sync(0xffffffffu, p, 1);
        p += __shfl_xor_sync(0xffffffffu, p, 2);
        if (qq == 0) m1[od] = fmaxf(p + bm1[od], 0.f);
    }
    __syncthreads();

    if (wid < OUTD) {
        const int o = wid;
        const float* Eo = g_E + o*HID;
        const float* wp = Wp + (size_t)o*(MLP_H + HID + OUTD);
        float p = 0.f;
        #pragma unroll
        for (int c = 0; c < 8; c++)
            p = fmaf(Eo[c*32 + lane], sm[c*32 + lane], p);
        p = fmaf(wp[lane],      m1[lane],      p);
        p = fmaf(wp[32 + lane], m1[32 + lane], p);
        if (lane < OUTD) p = fmaf(wp[320 + lane], glo8[lane], p);
        #pragma unroll
        for (int s = 16; s > 0; s >>= 1) p += __shfl_xor_sync(0xffffffffu, p, s);
        if (lane == 0) out[b*OUTD + o] = p + bp[o] + g_c0[o];
    }
}

// ---------------- launch ----------------
extern "C" void kernel_launch(void* const* d_in, const int* in_sizes, int n_in,
                              void* d_out, int out_size) {
    (void)in_sizes; (void)n_in; (void)out_size;
    const float* x   = (const float*)d_in[0];
    const float* W1  = (const float*)d_in[1];
    const float* b1  = (const float*)d_in[2];
    const float* W2  = (const float*)d_in[3];
    const float* b2  = (const float*)d_in[4];
    const float* Wfc = (const float*)d_in[5];
    const float* bfc = (const float*)d_in[6];
    const float* Wg  = (const float*)d_in[7];
    const float* bg  = (const float*)d_in[8];
    const float* Wm0 = (const float*)d_in[9];
    const float* bm0 = (const float*)d_in[10];
    const float* Wm1 = (const float*)d_in[11];
    const float* bm1 = (const float*)d_in[12];
    const float* Wp  = (const float*)d_in[13];
    const float* bp  = (const float*)d_in[14];
    float* out = (float*)d_out;

    // smallest C with sqrtf(C) >= 0.3f  =>  (d2 < C) <=> (sqrtf(d2) < 0.3f)
    float C = 0.09f;
    while (sqrtf(C) >= 0.3f) C = nextafterf(C, 0.0f);
    while (sqrtf(C) <  0.3f) C = nextafterf(C, 1.0f);

    kAdj <<<dim3(8, BATCH), 512>>>(x, C);
    kMlp1<<<dim3(7, 8), 512>>>(x, Wm0);
    kFold<<<OUTD, 512>>>(Wfc, W2, b2, bfc, Wp);
    k2a  <<<dim3(4, BATCH), 512>>>(x, W1, b1);
    k2b  <<<BATCH, 1024>>>(x, Wg, bg, Wm1, bm1, bm0, Wp, bp, out);
}

// round 17
// speedup vs baseline: 1.2657x; 1.2657x over previous
#include <cuda_runtime.h>
#include <cuda_bf16.h>
#include <cmath>

#define BATCH 32
#define NPTS  1024
#define FDIM  7
#define HID   256
#define MLP_H 64
#define OUTD  8

// ---------------- scratch (device globals) ----------------
__device__ unsigned g_adjw[BATCH*32*NPTS];        // adjacency bitmask, 4 MB
__device__ float    g_dinv[BATCH*NPTS];           // 1/sqrt(degree)
__device__ float    g_maxpart[BATCH*8];
__device__ float    g_mlpPart[BATCH*7*MLP_H];
__device__ float    g_upart[BATCH*16*HID];
__device__ float    g_E[OUTD*HID];                // folded GCN head: Wp_gcn@Wfc@W2
__device__ float    g_c0[OUTD];                   // folded GCN bias contribution

// ---------------- kA: fused adjacency(8-slice) + MLP layer-1 + GCN-head fold ----------------
// blocks [0,256): adjacency (b = bx>>3, slice = bx&7), 2 blocks/SM resident
// blocks [256,312): mlp1 partials (7 slices x 8 batch-groups)
// blocks [312,320): GCN-head fold, one block per output row o
__global__ void __launch_bounds__(512, 2)
kA(const float* __restrict__ x, const float* __restrict__ Wm0,
   const float* __restrict__ Wfc, const float* __restrict__ W2,
   const float* __restrict__ b2, const float* __restrict__ bfc,
   const float* __restrict__ Wp, float C) {
    const int tid = threadIdx.x;
    const int lane = tid & 31, w = tid >> 5;      // 16 warps
    __shared__ float4 S4[NPTS];                   // 16KB, role-shared
    __shared__ float wred[16];

    const int bx = blockIdx.x;
    if (bx < 256) {
        // ---------------- adjacency: upper-tri tiles, sign-bit build, transpose mirror ----------------
        const int b = bx >> 3, sl = bx & 7;
        for (int i = tid; i < NPTS; i += 512) {
            const float* xp = x + (size_t)(b*NPTS + i)*FDIM;
            const float p0 = xp[1], p1 = xp[2];
            const float n = fmaf(p0, p0, p1*p1);
            S4[i] = make_float4(p0, p1, n, C - n);
        }
        __syncthreads();

        const int ww = sl*16 + w;                 // warp id within batch, 0..127
        int L = (ww*528) >> 7;
        const int Lend = ((ww + 1)*528) >> 7;     // ~4.1 tiles per warp

        int jb = 0, rem = L;
        while (rem >= 32 - jb) { rem -= 32 - jb; jb++; }
        int kb = jb + rem;

        unsigned* __restrict__ aw = &g_adjw[(size_t)b*32*NPTS];
        float mx0 = -1e30f, mx1 = -1e30f;         // track max(d2 - C)

        for (; L < Lend; L++) {
            const float4 pk = S4[kb*32 + lane];
            const float a0 = -2.0f*pk.x, a1 = -2.0f*pk.y, nk = pk.z;
            const float4* Pj = &S4[jb*32];

            unsigned w0 = 0, w1 = 0;
            #pragma unroll
            for (int t = 0; t < 32; t++) {
                const float4 pj = Pj[t];                      // broadcast LDS.128
                float u = fmaf(a0, pj.x, nk);
                u = fmaf(a1, pj.y, u);                        // u = nk - 2 pj.pk
                const float dlt = u - pj.w;                   // = d2 - C; sign <=> d2 < C
                const unsigned bit = (__float_as_uint(dlt) >> (31 - t)) & (1u << t);
                if (t & 1) { w1 |= bit; mx1 = fmaxf(mx1, dlt); }
                else       { w0 |= bit; mx0 = fmaxf(mx0, dlt); }
            }
            const unsigned word = w0 | w1;
            aw[(jb << 10) + kb*32 + lane] = word;             // row kb*32+lane, colblock jb

            if (jb != kb) {
                unsigned xw = word;                           // 32x32 bit transpose
                #pragma unroll
                for (int i2 = 4; i2 >= 0; i2--) {
                    const int s = 1 << i2;
                    const unsigned msk = (i2 == 4) ? 0x0000FFFFu :
                                         (i2 == 3) ? 0x00FF00FFu :
                                         (i2 == 2) ? 0x0F0F0F0Fu :
                                         (i2 == 1) ? 0x33333333u : 0x55555555u;
                    const unsigned y = __shfl_xor_sync(0xffffffffu, xw, s);
                    xw = (lane & s) ? ((xw & ~msk) | ((y >> s) & msk))
                                    : ((xw & msk) | ((y & msk) << s));
                }
                aw[(kb << 10) + jb*32 + lane] = xw;           // row jb*32+lane, colblock kb
            }
            if (++kb == 32) { jb++; kb = jb; }
        }

        float dmax = fmaxf(mx0, mx1);
        #pragma unroll
        for (int s = 16; s > 0; s >>= 1)
            dmax = fmaxf(dmax, __shfl_xor_sync(0xffffffffu, dmax, s));
        if (lane == 0) wred[w] = dmax;
        __syncthreads();
        if (tid == 0) {
            float mx = wred[0];
            #pragma unroll
            for (int i = 1; i < 16; i++) mx = fmaxf(mx, wred[i]);
            g_maxpart[b*8 + sl] = C + mx;                     // back to max(d2)
        }
    } else if (bx < 312) {
        // ---------------- mlp1 partials ----------------
        const int mi = bx - 256;
        const int sl = mi % 7, b0 = (mi / 7)*4;
        float4 (*sx)[256] = reinterpret_cast<float4(*)[256]>(S4);
        for (int q = tid; q < 1024; q += 512) {
            const int bb = q >> 8, e = q & 255;
            sx[bb][e] = ((const float4*)(x + (size_t)(b0 + bb)*(NPTS*FDIM) + sl*1024))[e];
        }
        __syncthreads();

        const int h0 = w*4;
        float acc[4][4];
        #pragma unroll
        for (int r = 0; r < 4; r++)
            #pragma unroll
            for (int bb = 0; bb < 4; bb++) acc[r][bb] = 0.f;

        #pragma unroll
        for (int it = 0; it < 8; it++) {
            const int e = it*32 + lane;
            const float4 x0 = sx[0][e], x1 = sx[1][e], x2 = sx[2][e], x3 = sx[3][e];
            #pragma unroll
            for (int r = 0; r < 4; r++) {
                const float4 wv = ((const float4*)(Wm0 + (size_t)(h0 + r)*(NPTS*FDIM) + sl*1024))[e];
                acc[r][0] = fmaf(wv.x, x0.x, acc[r][0]); acc[r][0] = fmaf(wv.y, x0.y, acc[r][0]);
                acc[r][0] = fmaf(wv.z, x0.z, acc[r][0]); acc[r][0] = fmaf(wv.w, x0.w, acc[r][0]);
                acc[r][1] = fmaf(wv.x, x1.x, acc[r][1]); acc[r][1] = fmaf(wv.y, x1.y, acc[r][1]);
                acc[r][1] = fmaf(wv.z, x1.z, acc[r][1]); acc[r][1] = fmaf(wv.w, x1.w, acc[r][1]);
                acc[r][2] = fmaf(wv.x, x2.x, acc[r][2]); acc[r][2] = fmaf(wv.y, x2.y, acc[r][2]);
                acc[r][2] = fmaf(wv.z, x2.z, acc[r][2]); acc[r][2] = fmaf(wv.w, x2.w, acc[r][2]);
                acc[r][3] = fmaf(wv.x, x3.x, acc[r][3]); acc[r][3] = fmaf(wv.y, x3.y, acc[r][3]);
                acc[r][3] = fmaf(wv.z, x3.z, acc[r][3]); acc[r][3] = fmaf(wv.w, x3.w, acc[r][3]);
            }
        }
        #pragma unroll
        for (int r = 0; r < 4; r++)
            #pragma unroll
            for (int bb = 0; bb < 4; bb++) {
                float v = acc[r][bb];
                #pragma unroll
                for (int s = 16; s > 0; s >>= 1) v += __shfl_xor_sync(0xffffffffu, v, s);
                if (lane == 0) g_mlpPart[((b0 + bb)*7 + sl)*MLP_H + h0 + r] = v;
            }
    } else {
        // ---------------- GCN-head fold: E[o,:] = (Wp_gcn[o,:]@Wfc)@W2 ----------------
        const int o = bx - 312;
        const float* wp = Wp + (size_t)o*(MLP_H + HID + OUTD) + MLP_H;   // Wp_gcn row o
        float* sA = (float*)S4;

        if (tid < HID) {
            float a = 0.f;
            #pragma unroll 8
            for (int k = 0; k < HID; k++)
                a = fmaf(wp[k], Wfc[(size_t)k*HID + tid], a);
            sA[tid] = a;
        }
        __syncthreads();

        float v = (tid < HID) ? fmaf(sA[tid], b2[tid], wp[tid]*bfc[tid]) : 0.f;
        #pragma unroll
        for (int s = 16; s > 0; s >>= 1) v += __shfl_xor_sync(0xffffffffu, v, s);
        if (lane == 0) wred[w] = v;
        __syncthreads();
        if (tid == 0) {
            float c = 0.f;
            #pragma unroll
            for (int i = 0; i < 8; i++) c += wred[i];
            g_c0[o] = c;
        }

        if (tid < HID) {
            float e = 0.f;
            #pragma unroll 8
            for (int k = 0; k < HID; k++)
                e = fmaf(sA[k], W2[(size_t)k*HID + tid], e);
            g_E[o*HID + tid] = e;
        }
    }
}

// ---------------- kDeg: degrees -> dinv, computed ONCE ----------------
// grid (4, BATCH) x 256thr, thread per row; coalesced word reads
__global__ void __launch_bounds__(256)
kDeg() {
    const int b = blockIdx.y;
    const int r = blockIdx.x*256 + threadIdx.x;
    int cnt = 0;
    #pragma unroll
    for (int cb = 0; cb < 32; cb++)
        cnt += __popc(g_adjw[(((size_t)b*32 + cb) << 10) + r]);
    g_dinv[b*NPTS + r] = 1.0f / sqrtf((float)cnt);
}

// ---------------- k2a: gather (4 thr/row) + u-partials ----------------
// grid (4, BATCH) x 1024thr
__global__ void __launch_bounds__(1024)
k2a(const float* __restrict__ x,
    const float* __restrict__ W1, const float* __restrict__ b1) {
    const int q = blockIdx.x, b = blockIdx.y;     // quarter q of batch b
    const int t = threadIdx.x;

    __shared__ float sp0[NPTS], sp1[NPTS], sdv[NPTS];
    __shared__ float4 P4[256];                    // (pp0, pp1, cc, 0) for own rows

    // one row per thread: points + dinv
    {
        const float* xp = x + (size_t)(b*NPTS + t)*FDIM;
        sp0[t] = xp[1];
        sp1[t] = xp[2];
        sdv[t] = g_dinv[b*NPTS + t];
    }
    __syncthreads();

    // gather: 4 threads per row (adjacent lanes), 8 words each
    {
        const int rloc = t >> 2, sub = t & 3;
        const int rr = q*256 + rloc;
        float s0 = 0.f, s1 = 0.f, ss = 0.f;
        for (int cb = sub*8; cb < sub*8 + 8; cb++) {
            unsigned m = g_adjw[(((size_t)b*32 + cb) << 10) + rr];
            const int base = cb*32;
            while (m) {
                const int i = __ffs(m) - 1;
                m &= m - 1;
                const int k = base + i;
                const float d = sdv[k];
                s0 = fmaf(d, sp0[k], s0);
                s1 = fmaf(d, sp1[k], s1);
                ss += d;
            }
        }
        // reduce over the 4 subs (adjacent lanes)
        s0 += __shfl_xor_sync(0xffffffffu, s0, 1);
        s0 += __shfl_xor_sync(0xffffffffu, s0, 2);
        s1 += __shfl_xor_sync(0xffffffffu, s1, 1);
        s1 += __shfl_xor_sync(0xffffffffu, s1, 2);
        ss += __shfl_xor_sync(0xffffffffu, ss, 1);
        ss += __shfl_xor_sync(0xffffffffu, ss, 2);
        if (sub == 0) {
            const float dj = sdv[rr];
            P4[rloc] = make_float4(dj*s0, dj*s1, dj*ss, 0.f);
        }
    }
    __syncthreads();

    // u-partial: dim d over this block's 256 points, split into 4 groups of 64
    {
        const int d = t & 255, g = t >> 8;
        const float w0 = W1[2*d], w1 = W1[2*d + 1], bd = b1[d];
        const int pb = g*64;
        float a0 = 0.f, a1 = 0.f;
        #pragma unroll 4
        for (int i = 0; i < 32; i++) {
            const float4 v0 = P4[pb + i];
            const float4 v1 = P4[pb + 32 + i];
            float t0 = fmaf(w1, v0.y, fmaf(w0, v0.x, bd)); t0 = fmaxf(t0, 0.f);
            float t1 = fmaf(w1, v1.y, fmaf(w0, v1.x, bd)); t1 = fmaxf(t1, 0.f);
            a0 = fmaf(v0.z, t0, a0);
            a1 = fmaf(v1.z, t1, a1);
        }
        g_upart[((size_t)b*16 + q*4 + g)*HID + d] = a0 + a1;
    }
}

// ---------------- k2b: speed, m, glo, mlp finish, folded-head output ----------------
__global__ void __launch_bounds__(1024)
k2b(const float* __restrict__ x,
    const float* __restrict__ Wg, const float* __restrict__ bgv,
    const float* __restrict__ Wm1, const float* __restrict__ bm1,
    const float* __restrict__ bm0,
    const float* __restrict__ Wp, const float* __restrict__ bp,
    float* __restrict__ out) {
    const int b = blockIdx.x;
    const int t = threadIdx.x;
    const int lane = t & 31, wid = t >> 5;

    __shared__ float red[32];
    __shared__ float sm[HID];
    __shared__ float m0[MLP_H], m1[MLP_H], glo8[OUTD];
    __shared__ float sgl[2];

    {
        const float* xp = x + (size_t)(b*NPTS + t)*FDIM;
        const float x3 = xp[3], x4 = xp[4];
        float sp = sqrtf(fmaf(x3, x3, x4*x4));
        #pragma unroll
        for (int s = 16; s > 0; s >>= 1) sp += __shfl_xor_sync(0xffffffffu, sp, s);
        if (lane == 0) red[wid] = sp;
    }
    if (t < HID) {
        float u = 0.f;
        #pragma unroll
        for (int c = 0; c < 16; c++) u += g_upart[((size_t)b*16 + c)*HID + t];
        sm[t] = u * (1.0f/1024.0f);
    } else if (t >= 512 && t < 512 + MLP_H) {
        const int h = t - 512;
        float a = bm0[h];
        #pragma unroll
        for (int s = 0; s < 7; s++) a += g_mlpPart[(b*7 + s)*MLP_H + h];
        m0[h] = fmaxf(a, 0.f);
    }
    __syncthreads();

    if (wid == 0) {
        float v = red[lane];
        #pragma unroll
        for (int s = 16; s > 0; s >>= 1) v += __shfl_xor_sync(0xffffffffu, v, s);
        if (lane == 0) {
            float mx = g_maxpart[b*8];
            #pragma unroll
            for (int i = 1; i < 8; i++) mx = fmaxf(mx, g_maxpart[b*8 + i]);
            sgl[0] = v * (1.0f/1024.0f);
            sgl[1] = 1.0f / sqrtf(mx);
        }
    }
    __syncthreads();

    if (t >= 768 && t < 768 + OUTD) {
        const int o = t - 768;
        const float ge = fmaf(Wg[2*o], sgl[0], fmaf(Wg[2*o + 1], sgl[1], bgv[o]));
        glo8[o] = fmaxf(ge, 0.f);
    }
    if (t < 256) {
        const int od = t >> 2, qq = t & 3;
        const float4* wr4 = (const float4*)(Wm1 + (size_t)od*MLP_H + qq*16);
        const float4* mm4 = (const float4*)(m0 + qq*16);
        float p = 0.f;
        #pragma unroll
        for (int e = 0; e < 4; e++) {
            const float4 wv = wr4[e], mv = mm4[e];
            p = fmaf(wv.x, mv.x, p); p = fmaf(wv.y, mv.y, p);
            p = fmaf(wv.z, mv.z, p); p = fmaf(wv.w, mv.w, p);
        }
        p += __shfl_xor_sync(0xffffffffu, p, 1);
        p += __shfl_xor_sync(0xffffffffu, p, 2);
        if (qq == 0) m1[od] = fmaxf(p + bm1[od], 0.f);
    }
    __syncthreads();

    if (wid < OUTD) {
        const int o = wid;
        const float* Eo = g_E + o*HID;
        const float* wp = Wp + (size_t)o*(MLP_H + HID + OUTD);
        float p = 0.f;
        #pragma unroll
        for (int c = 0; c < 8; c++)
            p = fmaf(Eo[c*32 + lane], sm[c*32 + lane], p);
        p = fmaf(wp[lane],      m1[lane],      p);
        p = fmaf(wp[32 + lane], m1[32 + lane], p);
        if (lane < OUTD) p = fmaf(wp[320 + lane], glo8[lane], p);
        #pragma unroll
        for (int s = 16; s > 0; s >>= 1) p += __shfl_xor_sync(0xffffffffu, p, s);
        if (lane == 0) out[b*OUTD + o] = p + bp[o] + g_c0[o];
    }
}

// ---------------- launch ----------------
extern "C" void kernel_launch(void* const* d_in, const int* in_sizes, int n_in,
                              void* d_out, int out_size) {
    (void)in_sizes; (void)n_in; (void)out_size;
    const float* x   = (const float*)d_in[0];
    const float* W1  = (const float*)d_in[1];
    const float* b1  = (const float*)d_in[2];
    const float* W2  = (const float*)d_in[3];
    const float* b2  = (const float*)d_in[4];
    const float* Wfc = (const float*)d_in[5];
    const float* bfc = (const float*)d_in[6];
    const float* Wg  = (const float*)d_in[7];
    const float* bg  = (const float*)d_in[8];
    const float* Wm0 = (const float*)d_in[9];
    const float* bm0 = (const float*)d_in[10];
    const float* Wm1 = (const float*)d_in[11];
    const float* bm1 = (const float*)d_in[12];
    const float* Wp  = (const float*)d_in[13];
    const float* bp  = (const float*)d_in[14];
    float* out = (float*)d_out;

    // smallest C with sqrtf(C) >= 0.3f  =>  (d2 < C) <=> (sqrtf(d2) < 0.3f)
    float C = 0.09f;
    while (sqrtf(C) >= 0.3f) C = nextafterf(C, 0.0f);
    while (sqrtf(C) <  0.3f) C = nextafterf(C, 1.0f);

    kA  <<<320, 512>>>(x, Wm0, Wfc, W2, b2, bfc, Wp, C);
    kDeg<<<dim3(4, BATCH), 256>>>();
    k2a <<<dim3(4, BATCH), 1024>>>(x, W1, b1);
    k2b <<<BATCH, 1024>>>(x, Wg, bg, Wm1, bm1, bm0, Wp, bp, out);
}